// round 3
// baseline (speedup 1.0000x reference)
#include <cuda_runtime.h>

#define B_   8192
#define D_   4096
#define E_   64
#define BM   32
#define KC   64
#define NCH  (D_ / KC)   // 64 chunks

// 128 threads, 2 CTAs/SM. Each CTA: BM=32 rows x E=64 experts, full K reduction.
// Thread micro-tile: 4 rows x 4 experts (16 accumulators).
__global__ __launch_bounds__(128, 2)
void router_kernel(const float* __restrict__ x,
                   const float* __restrict__ gw,
                   const float* __restrict__ temp,
                   float* __restrict__ out,
                   int out_size)
{
    __shared__ float xs[BM][KC + 1];   // +1 pad: conflict-light reads
    __shared__ float ws[E_][KC + 1];
    __shared__ float ls[BM][E_ + 1];   // logits, +1 pad for row scans
    __shared__ float w1s[BM], w2s[BM];
    __shared__ int   i1s[BM], i2s[BM];

    const int tid = threadIdx.x;
    const int bm0 = blockIdx.x * BM;

    // global-load mapping: 16 float4 per 64-wide k-chunk row
    const int r0 = tid >> 4;    // 0..7
    const int c4 = tid & 15;    // 0..15

    // compute mapping: 8 row-groups x 16 expert-groups
    const int m0 = (tid >> 4) * 4;   // 0,4,...,28
    const int e0 = (tid & 15) * 4;   // 0,4,...,60

    float acc[4][4];
    #pragma unroll
    for (int i = 0; i < 4; i++)
        #pragma unroll
        for (int j = 0; j < 4; j++) acc[i][j] = 0.0f;

    float4 xr[4], wr[8];
    const float* xg = x + (size_t)bm0 * D_;

    // ---- prologue: stage chunk 0 into registers ----
    #pragma unroll
    for (int i = 0; i < 4; i++)
        xr[i] = *reinterpret_cast<const float4*>(xg + (size_t)(r0 + i * 8) * D_ + c4 * 4);
    #pragma unroll
    for (int i = 0; i < 8; i++)
        wr[i] = *reinterpret_cast<const float4*>(gw + (size_t)(r0 + i * 8) * D_ + c4 * 4);

    // ---- main K loop ----
    for (int c = 0; c < NCH; ++c) {
        __syncthreads();   // previous chunk's compute done before overwrite

        #pragma unroll
        for (int i = 0; i < 4; i++) {
            const int row = r0 + i * 8;
            xs[row][c4 * 4 + 0] = xr[i].x;
            xs[row][c4 * 4 + 1] = xr[i].y;
            xs[row][c4 * 4 + 2] = xr[i].z;
            xs[row][c4 * 4 + 3] = xr[i].w;
        }
        #pragma unroll
        for (int i = 0; i < 8; i++) {
            const int row = r0 + i * 8;
            ws[row][c4 * 4 + 0] = wr[i].x;
            ws[row][c4 * 4 + 1] = wr[i].y;
            ws[row][c4 * 4 + 2] = wr[i].z;
            ws[row][c4 * 4 + 3] = wr[i].w;
        }
        __syncthreads();

        // prefetch next chunk into registers; LDG latency hidden by compute below
        if (c + 1 < NCH) {
            const int ko = (c + 1) * KC;
            #pragma unroll
            for (int i = 0; i < 4; i++)
                xr[i] = *reinterpret_cast<const float4*>(xg + (size_t)(r0 + i * 8) * D_ + ko + c4 * 4);
            #pragma unroll
            for (int i = 0; i < 8; i++)
                wr[i] = *reinterpret_cast<const float4*>(gw + (size_t)(r0 + i * 8) * D_ + ko + c4 * 4);
        }

        #pragma unroll 16
        for (int k = 0; k < KC; k++) {
            const float a0 = xs[m0 + 0][k];
            const float a1 = xs[m0 + 1][k];
            const float a2 = xs[m0 + 2][k];
            const float a3 = xs[m0 + 3][k];
            const float b0 = ws[e0 + 0][k];
            const float b1 = ws[e0 + 1][k];
            const float b2 = ws[e0 + 2][k];
            const float b3 = ws[e0 + 3][k];
            acc[0][0] += a0 * b0; acc[0][1] += a0 * b1; acc[0][2] += a0 * b2; acc[0][3] += a0 * b3;
            acc[1][0] += a1 * b0; acc[1][1] += a1 * b1; acc[1][2] += a1 * b2; acc[1][3] += a1 * b3;
            acc[2][0] += a2 * b0; acc[2][1] += a2 * b1; acc[2][2] += a2 * b2; acc[2][3] += a2 * b3;
            acc[3][0] += a3 * b0; acc[3][1] += a3 * b1; acc[3][2] += a3 * b2; acc[3][3] += a3 * b3;
        }
    }

    // ---- stash logits to smem ----
    __syncthreads();
    #pragma unroll
    for (int i = 0; i < 4; i++)
        #pragma unroll
        for (int j = 0; j < 4; j++)
            ls[m0 + i][e0 + j] = acc[i][j];
    __syncthreads();

    // ---- per-row top-2 + softmax (threads 0..31) ----
    if (tid < BM) {
        const float invT = 1.0f / temp[0];
        float best1 = -3.402823466e+38f, best2 = -3.402823466e+38f;
        int b1 = 0, b2 = 0;
        #pragma unroll 8
        for (int e = 0; e < E_; e++) {
            const float v = ls[tid][e];
            if (v > best1) { best2 = best1; b2 = b1; best1 = v; b1 = e; }
            else if (v > best2) { best2 = v; b2 = e; }
        }
        // softmax over [best1, best2] after /T; stable 2-way form
        const float d = (best2 - best1) * invT;   // <= 0
        const float e2 = __expf(d);
        const float w1 = 1.0f / (1.0f + e2);
        w1s[tid] = w1;
        w2s[tid] = 1.0f - w1;
        i1s[tid] = b1;
        i2s[tid] = b2;
    }
    __syncthreads();

    // ---- coalesced routing-matrix write: BM*E_ = 2048 floats, 16 per thread ----
    #pragma unroll
    for (int j = 0; j < 16; j++) {
        const int idx = j * 128 + tid;      // 0..2047
        const int row = idx >> 6;           // /64
        const int e   = idx & 63;
        float v = 0.0f;
        if (e == i1s[row]) v = w1s[row];
        else if (e == i2s[row]) v = w2s[row];
        out[(size_t)(bm0 + row) * E_ + e] = v;
    }

    // ---- top_idx output (as float), appended after the B*E routing matrix ----
    if (out_size >= B_ * E_ + B_ * 2 && tid < BM * 2) {
        const int row = tid >> 1;
        const int kk  = tid & 1;
        out[(size_t)B_ * E_ + (size_t)(bm0 + row) * 2 + kk] =
            (float)(kk ? i2s[row] : i1s[row]);
    }
}

extern "C" void kernel_launch(void* const* d_in, const int* in_sizes, int n_in,
                              void* d_out, int out_size)
{
    const float* x    = (const float*)d_in[0];
    const float* gw   = (const float*)d_in[1];
    const float* temp = (const float*)d_in[2];
    float* out = (float*)d_out;

    router_kernel<<<B_ / BM, 128>>>(x, gw, temp, out, out_size);
}

// round 7
// speedup vs baseline: 1.2475x; 1.2475x over previous
#include <cuda_runtime.h>
#include <cstdint>

#define B_    8192
#define D_    4096
#define E_    64
#define TM    64                    // rows per CTA
#define KC    64                    // K per chunk
#define NCH   (D_ / KC)             // 64 chunks
#define STAGE_BYTES 65536u          // A(2 limbs,32KB) + W(2 limbs,32KB)
#define W_OFF 32768u
#define SM_DYN (2u * STAGE_BYTES)   // 128KB double buffer

// pre-split gate_w, B-fragment order: [chunk][limb(2)][n8(8)][ks(8)][lane(32)][slot(2)]
__device__ __align__(16) uint32_t g_w2[NCH][8192];

__device__ __forceinline__ uint32_t f2tf32(float v) {
    uint32_t r; asm("cvt.rna.tf32.f32 %0, %1;" : "=r"(r) : "f"(v)); return r;
}

#define MMA_TF32(d, a, b)                                              \
    asm volatile(                                                      \
        "mma.sync.aligned.m16n8k8.row.col.f32.tf32.tf32.f32 "          \
        "{%0,%1,%2,%3}, {%4,%5,%6,%7}, {%8,%9}, {%0,%1,%2,%3};"        \
        : "+f"((d)[0]), "+f"((d)[1]), "+f"((d)[2]), "+f"((d)[3])       \
        : "r"((a).x), "r"((a).y), "r"((a).z), "r"((a).w),              \
          "r"((b).x), "r"((b).y))

// ---------------- prep: split gate_w into 2 tf32 limbs, B-fragment layout ----------------
__global__ void prep_w(const float* __restrict__ gw) {
    const int ch = blockIdx.x;
    const int t  = threadIdx.x;
    #pragma unroll
    for (int i = 0; i < 4; i++) {
        const int slot = i * 256 + t;            // 1024 float4 slots = 64e x 16kq
        const int e = slot >> 4, kq = slot & 15, k0 = kq * 4;
        const float4 v = *reinterpret_cast<const float4*>(
            gw + (size_t)e * D_ + (size_t)ch * KC + k0);
        const int n8 = e >> 3, ks = k0 >> 3, kh = (k0 >> 2) & 1;
        const float vv[4] = {v.x, v.y, v.z, v.w};
        #pragma unroll
        for (int j = 0; j < 4; j++) {
            const int lane = (e & 7) * 4 + j;
            const uint32_t hi = f2tf32(vv[j]);
            const uint32_t lo = f2tf32(vv[j] - __uint_as_float(hi));
            const int off = ((n8 * 8 + ks) * 32 + lane) * 2 + kh;
            g_w2[ch][off]        = hi;           // limb 0
            g_w2[ch][off + 4096] = lo;           // limb 1
        }
    }
}

// ---------------- main: 3xTF32 HMMA GEMM + fused top-2 softmax router ----------------
__global__ __launch_bounds__(256, 1)
void router_mm(const float* __restrict__ x,
               const float* __restrict__ temp,
               float* __restrict__ out, int out_size)
{
    extern __shared__ uint8_t sm[];
    __shared__ float ls[TM][E_ + 2];
    __shared__ float w1s[TM], w2s[TM];
    __shared__ int   i1s[TM], i2s[TM];

    const int tid = threadIdx.x;
    const int wid = tid >> 5, lid = tid & 31;
    const int wm = wid >> 1, wn = wid & 1;       // 4x2 warp grid
    const int bm0 = blockIdx.x * TM;
    const float* xg = x + (size_t)bm0 * D_;

    float acc[4][4] = {};
    float4 xr[4];
    uint4  wrq[8];

    // global stage: x chunk (4 float4) + pre-split W chunk (8 uint4)
    auto gload = [&](int c) {
        #pragma unroll
        for (int i = 0; i < 4; i++) {
            const int s = i * 256 + tid;
            const int row = s >> 4, kq = s & 15;
            xr[i] = *reinterpret_cast<const float4*>(
                xg + (size_t)row * D_ + (size_t)c * KC + kq * 4);
        }
        const uint4* wsrc = reinterpret_cast<const uint4*>(g_w2[c]);
        #pragma unroll
        for (int i = 0; i < 8; i++) wrq[i] = wsrc[i * 256 + tid];
    };

    // convert x -> 2 tf32 limbs in A-fragment order; copy W verbatim
    auto cstore = [&](int st) {
        uint32_t* A0 = reinterpret_cast<uint32_t*>(sm + st * STAGE_BYTES);
        uint32_t* A1 = A0 + 4096;
        #pragma unroll
        for (int i = 0; i < 4; i++) {
            const int s = i * 256 + tid;
            const int row = s >> 4, kq = s & 15, k0 = kq * 4;
            const int wmr = row >> 4, r16 = row & 15;
            const int g = r16 & 7, hm = r16 >> 3;
            const int ks = k0 >> 3, kh = (k0 >> 2) & 1;
            const int sl = hm + 2 * kh;                       // a0..a3 slot
            const int base = ((wmr * 8 + ks) * 32 + g * 4) * 4 + sl;
            const float vv[4] = {xr[i].x, xr[i].y, xr[i].z, xr[i].w};
            #pragma unroll
            for (int j = 0; j < 4; j++) {
                const uint32_t hi = f2tf32(vv[j]);
                const uint32_t lo = f2tf32(vv[j] - __uint_as_float(hi));
                A0[base + j * 4] = hi;
                A1[base + j * 4] = lo;
            }
        }
        uint4* W = reinterpret_cast<uint4*>(sm + st * STAGE_BYTES + W_OFF);
        #pragma unroll
        for (int i = 0; i < 8; i++) W[i * 256 + tid] = wrq[i];
    };

    auto compute = [&](int st) {
        const uint32_t* A0 = reinterpret_cast<const uint32_t*>(sm + st * STAGE_BYTES);
        const uint32_t* A1 = A0 + 4096;
        const uint32_t* W0 = reinterpret_cast<const uint32_t*>(sm + st * STAGE_BYTES + W_OFF);
        const uint32_t* W1 = W0 + 4096;
        #pragma unroll
        for (int ks = 0; ks < 8; ks++) {
            const uint4 ah = *reinterpret_cast<const uint4*>(A0 + ((wm * 8 + ks) * 32 + lid) * 4);
            const uint4 al = *reinterpret_cast<const uint4*>(A1 + ((wm * 8 + ks) * 32 + lid) * 4);
            uint2 bh[4], bl[4];
            #pragma unroll
            for (int t = 0; t < 4; t++) {
                const int n8 = wn * 4 + t;
                bh[t] = *reinterpret_cast<const uint2*>(W0 + ((n8 * 8 + ks) * 32 + lid) * 2);
                bl[t] = *reinterpret_cast<const uint2*>(W1 + ((n8 * 8 + ks) * 32 + lid) * 2);
            }
            #pragma unroll
            for (int t = 0; t < 4; t++) MMA_TF32(acc[t], ah, bh[t]);   // hi*hi
            #pragma unroll
            for (int t = 0; t < 4; t++) MMA_TF32(acc[t], al, bh[t]);   // lo*hi
            #pragma unroll
            for (int t = 0; t < 4; t++) MMA_TF32(acc[t], ah, bl[t]);   // hi*lo
        }
    };

    // ---- pipeline: double-buffered, one sync per chunk ----
    gload(0);
    cstore(0);
    gload(1);
    __syncthreads();
    for (int c = 0; c < NCH; c++) {
        const int st = c & 1;
        if (c + 1 < NCH) cstore(st ^ 1);
        if (c + 2 < NCH) gload(c + 2);
        compute(st);
        __syncthreads();
    }

    // ---- dump logits: D frag c0/c1 are adjacent columns ----
    #pragma unroll
    for (int t = 0; t < 4; t++) {
        const int c0 = wn * 32 + t * 8 + 2 * (lid & 3);
        const int r0 = wm * 16 + (lid >> 2);
        *reinterpret_cast<float2*>(&ls[r0][c0])     = make_float2(acc[t][0], acc[t][1]);
        *reinterpret_cast<float2*>(&ls[r0 + 8][c0]) = make_float2(acc[t][2], acc[t][3]);
    }
    __syncthreads();

    // ---- per-row top-2 + 2-way softmax ----
    if (tid < TM) {
        float best1 = -3.402823466e+38f, best2 = -3.402823466e+38f;
        int b1 = 0, b2 = 0;
        #pragma unroll 8
        for (int e = 0; e < E_; e++) {
            const float v = ls[tid][e];
            if (v > best1) { best2 = best1; b2 = b1; best1 = v; b1 = e; }
            else if (v > best2) { best2 = v; b2 = e; }
        }
        const float invT = 1.0f / temp[0];
        const float dlt = (best2 - best1) * invT;   // <= 0
        const float w1 = 1.0f / (1.0f + __expf(dlt));
        w1s[tid] = w1; w2s[tid] = 1.0f - w1;
        i1s[tid] = b1; i2s[tid] = b2;
    }
    __syncthreads();

    // ---- coalesced routing-matrix write: 64*64 floats, 16/thread ----
    #pragma unroll
    for (int j = 0; j < 16; j++) {
        const int idx = j * 256 + tid;
        const int row = idx >> 6;
        const int e   = idx & 63;
        float v = 0.0f;
        if (e == i1s[row]) v = w1s[row];
        else if (e == i2s[row]) v = w2s[row];
        out[(size_t)(bm0 + row) * E_ + e] = v;
    }

    // ---- top_idx output (floats) after the B*E region ----
    if (out_size >= B_ * E_ + B_ * 2 && tid < TM * 2) {
        const int row = tid >> 1;
        const int kk  = tid & 1;
        out[(size_t)B_ * E_ + (size_t)(bm0 + row) * 2 + kk] =
            (float)(kk ? i2s[row] : i1s[row]);
    }
}

extern "C" void kernel_launch(void* const* d_in, const int* in_sizes, int n_in,
                              void* d_out, int out_size)
{
    const float* x    = (const float*)d_in[0];
    const float* gw   = (const float*)d_in[1];
    const float* temp = (const float*)d_in[2];
    float* out = (float*)d_out;

    cudaFuncSetAttribute(router_mm,
                         cudaFuncAttributeMaxDynamicSharedMemorySize, SM_DYN);

    prep_w<<<NCH, 256>>>(gw);
    router_mm<<<B_ / TM, 256, SM_DYN>>>(x, temp, out, out_size);
}